// round 1
// baseline (speedup 1.0000x reference)
#include <cuda_runtime.h>

// Lower-triangular matvec: y[i] = sum_{j<=i} W[i,j] * x[j]
// n = 8192, W row-major fp32.
//
// Strategy: HBM-bound streaming kernel. One block per row PAIR (i, n-1-i)
// so every block reads exactly n+1 W-elements (perfect load balance).
// float4 coalesced loads, dual block reduction.

#define NTHREADS 256

__global__ __launch_bounds__(NTHREADS, 8)
void tril_mv_kernel(const float* __restrict__ x,
                    const float* __restrict__ W,
                    float* __restrict__ y,
                    int n)
{
    __shared__ float red0[NTHREADS / 32];
    __shared__ float red1[NTHREADS / 32];

    const int b   = blockIdx.x;      // 0 .. n/2-1
    const int tid = threadIdx.x;

    const int r0 = b;
    const int r1 = n - 1 - b;

    const float4* __restrict__ x4 = reinterpret_cast<const float4*>(x);

    float acc0 = 0.0f;
    float acc1 = 0.0f;

    // ---- row r0 (length r0+1) ----
    {
        const int len = r0 + 1;
        const int nv4 = len >> 2;
        const float4* __restrict__ Wr =
            reinterpret_cast<const float4*>(W + (size_t)r0 * n);
        for (int k = tid; k < nv4; k += NTHREADS) {
            float4 w  = Wr[k];
            float4 xv = x4[k];
            acc0 += w.x * xv.x + w.y * xv.y + w.z * xv.z + w.w * xv.w;
        }
        const int tail = len & 3;
        if (tid < tail) {
            const int j = (nv4 << 2) + tid;
            acc0 += W[(size_t)r0 * n + j] * x[j];
        }
    }

    // ---- row r1 (length r1+1) ----
    {
        const int len = r1 + 1;
        const int nv4 = len >> 2;
        const float4* __restrict__ Wr =
            reinterpret_cast<const float4*>(W + (size_t)r1 * n);
        for (int k = tid; k < nv4; k += NTHREADS) {
            float4 w  = Wr[k];
            float4 xv = x4[k];
            acc1 += w.x * xv.x + w.y * xv.y + w.z * xv.z + w.w * xv.w;
        }
        const int tail = len & 3;
        if (tid < tail) {
            const int j = (nv4 << 2) + tid;
            acc1 += W[(size_t)r1 * n + j] * x[j];
        }
    }

    // ---- dual block reduction ----
    #pragma unroll
    for (int off = 16; off > 0; off >>= 1) {
        acc0 += __shfl_down_sync(0xffffffffu, acc0, off);
        acc1 += __shfl_down_sync(0xffffffffu, acc1, off);
    }
    const int warp = tid >> 5;
    const int lane = tid & 31;
    if (lane == 0) {
        red0[warp] = acc0;
        red1[warp] = acc1;
    }
    __syncthreads();

    if (warp == 0) {
        float a0 = (lane < NTHREADS / 32) ? red0[lane] : 0.0f;
        float a1 = (lane < NTHREADS / 32) ? red1[lane] : 0.0f;
        #pragma unroll
        for (int off = (NTHREADS / 64); off > 0; off >>= 1) {
            a0 += __shfl_down_sync(0xffffffffu, a0, off);
            a1 += __shfl_down_sync(0xffffffffu, a1, off);
        }
        if (lane == 0) {
            y[r0] = a0;
            y[r1] = a1;
        }
    }
}

extern "C" void kernel_launch(void* const* d_in, const int* in_sizes, int n_in,
                              void* d_out, int out_size) {
    const float* x = (const float*)d_in[0];   // [n]
    const float* W = (const float*)d_in[1];   // [n, n] row-major
    float*       y = (float*)d_out;           // [n]

    const int n = in_sizes[0];                // 8192 (even)

    tril_mv_kernel<<<n / 2, NTHREADS>>>(x, W, y, n);
}

// round 2
// speedup vs baseline: 1.0077x; 1.0077x over previous
#include <cuda_runtime.h>

// Lower-triangular matvec: y[i] = sum_{j<=i} W[i,j] * x[j]
// n = 8192, W row-major fp32 (lower triangle = 128 MB, streamed once).
//
// R2: HBM-bound. One block per row PAIR (i, n-1-i) -> every block reads
// exactly n+1 W-elements (perfect balance). Inner loop manually unrolled 4x
// with batched independent LDG.128s to maximize bytes-in-flight (the R1
// profile showed latency-limited DRAM at 55%). W loads use __ldcs
// (read-once streaming); x stays L1/L2-resident.

#define NTHREADS 256

__device__ __forceinline__ float dot4(float4 w, float4 v) {
    return w.x * v.x + w.y * v.y + w.z * v.z + w.w * v.w;
}

// Dot product of one W row (length len) with x, partial per thread.
__device__ __forceinline__ float row_dot(const float* __restrict__ Wr,
                                         const float* __restrict__ x,
                                         const float4* __restrict__ x4,
                                         int len, int tid)
{
    const float4* __restrict__ W4 = reinterpret_cast<const float4*>(Wr);
    const int nv4 = len >> 2;

    float a0 = 0.0f, a1 = 0.0f, a2 = 0.0f, a3 = 0.0f;

    int k = tid;
    // Main 4x-unrolled stream: 8 independent LDG.128 in flight per thread.
    for (; k + 3 * NTHREADS < nv4; k += 4 * NTHREADS) {
        float4 w0 = __ldcs(W4 + k);
        float4 w1 = __ldcs(W4 + k + NTHREADS);
        float4 w2 = __ldcs(W4 + k + 2 * NTHREADS);
        float4 w3 = __ldcs(W4 + k + 3 * NTHREADS);
        float4 v0 = x4[k];
        float4 v1 = x4[k + NTHREADS];
        float4 v2 = x4[k + 2 * NTHREADS];
        float4 v3 = x4[k + 3 * NTHREADS];
        a0 += dot4(w0, v0);
        a1 += dot4(w1, v1);
        a2 += dot4(w2, v2);
        a3 += dot4(w3, v3);
    }
    // Remainder float4s.
    for (; k < nv4; k += NTHREADS) {
        a0 += dot4(__ldcs(W4 + k), x4[k]);
    }

    float acc = (a0 + a1) + (a2 + a3);

    // Scalar tail (len % 4 elements).
    const int tail = len & 3;
    if (tid < tail) {
        const int j = (nv4 << 2) + tid;
        acc += Wr[j] * x[j];
    }
    return acc;
}

__global__ __launch_bounds__(NTHREADS)
void tril_mv_kernel(const float* __restrict__ x,
                    const float* __restrict__ W,
                    float* __restrict__ y,
                    int n)
{
    __shared__ float red0[NTHREADS / 32];
    __shared__ float red1[NTHREADS / 32];

    const int b   = blockIdx.x;      // 0 .. n/2-1
    const int tid = threadIdx.x;

    const int r0 = b;
    const int r1 = n - 1 - b;

    const float4* __restrict__ x4 = reinterpret_cast<const float4*>(x);

    float acc0 = row_dot(W + (size_t)r0 * n, x, x4, r0 + 1, tid);
    float acc1 = row_dot(W + (size_t)r1 * n, x, x4, r1 + 1, tid);

    // ---- dual block reduction ----
    #pragma unroll
    for (int off = 16; off > 0; off >>= 1) {
        acc0 += __shfl_down_sync(0xffffffffu, acc0, off);
        acc1 += __shfl_down_sync(0xffffffffu, acc1, off);
    }
    const int warp = tid >> 5;
    const int lane = tid & 31;
    if (lane == 0) {
        red0[warp] = acc0;
        red1[warp] = acc1;
    }
    __syncthreads();

    if (warp == 0) {
        float a0 = (lane < NTHREADS / 32) ? red0[lane] : 0.0f;
        float a1 = (lane < NTHREADS / 32) ? red1[lane] : 0.0f;
        #pragma unroll
        for (int off = (NTHREADS / 64); off > 0; off >>= 1) {
            a0 += __shfl_down_sync(0xffffffffu, a0, off);
            a1 += __shfl_down_sync(0xffffffffu, a1, off);
        }
        if (lane == 0) {
            y[r0] = a0;
            y[r1] = a1;
        }
    }
}

extern "C" void kernel_launch(void* const* d_in, const int* in_sizes, int n_in,
                              void* d_out, int out_size) {
    const float* x = (const float*)d_in[0];   // [n]
    const float* W = (const float*)d_in[1];   // [n, n] row-major
    float*       y = (float*)d_out;           // [n]

    const int n = in_sizes[0];                // 8192 (even)

    tril_mv_kernel<<<n / 2, NTHREADS>>>(x, W, y, n);
}